// round 12
// baseline (speedup 1.0000x reference)
#include <cuda_runtime.h>
#include <cstdint>

#define N_NODES  50000
#define N_EDGES  1600000
#define IN_CH    64
#define HID      16
#define NCLS     10
#define L2S      16   // layer-2 row stride: 64B sector-aligned rows (cols 10-15 zero)
#define TB       256

// ---------------- scratch (device globals; no allocations allowed) ----------
__device__ __align__(32) float g_y1  [N_NODES * HID];   // x @ w_rel1
__device__ __align__(32) float g_agg1[N_NODES * HID];   // x @ w_root1 + b (seed, then += scatter)
__device__ __align__(32) float g_y2  [N_NODES * L2S];   // h @ w_rel2, cols 10-15 = 0
__device__ __align__(32) float g_agg2[N_NODES * L2S];   // h @ w_root2 + b, cols 10-15 = 0
__device__ int g_is64;                                  // edge_index dtype flag
__device__ unsigned g_bar_cnt;                          // global barrier: monotonic arrivals
__device__ unsigned g_bar_base;                         // arrivals consumed by prior replays

// ---------------- vector reduction -------------------------------------------
__device__ __forceinline__ void red_add_v4(float* p, float4 v) {
    asm volatile("red.global.add.v4.f32 [%0], {%1,%2,%3,%4};"
                 :: "l"(p), "f"(v.x), "f"(v.y), "f"(v.z), "f"(v.w) : "memory");
}

__device__ __forceinline__ int clampN(int v) {
    return (int)min((unsigned)v, (unsigned)(N_NODES - 1));
}

// Fetch 4 consecutive edge srcs (or dsts) starting at elem index base (base%4==0).
__device__ __forceinline__ int4 load_idx4(const int* ei, int is64, int base) {
    if (!is64) {
        return __ldg(reinterpret_cast<const int4*>(ei + base));
    } else {
        const longlong2* p = reinterpret_cast<const longlong2*>(ei) + (base >> 1);
        longlong2 a = __ldg(p);
        longlong2 b = __ldg(p + 1);
        return make_int4((int)a.x, (int)a.y, (int)b.x, (int)b.y);
    }
}

// Generation global barrier. Monotonic counter; base read once per launch,
// advanced by block 0 at launch end, so it is graph-replay safe with no reset
// race. All blocks are co-resident by construction (grid = smCount*4,
// launch_bounds(256,4) => regs<=64, static smem ~9.6KB).
__device__ __forceinline__ void gbar(int gen, unsigned base, unsigned nb) {
    __syncthreads();
    if (threadIdx.x == 0) {
        __threadfence();
        atomicAdd(&g_bar_cnt, 1u);
        unsigned target = base + (unsigned)gen * nb;
        volatile unsigned* p = &g_bar_cnt;
        while (*p < target) __nanosleep(64);
        __threadfence();
    }
    __syncthreads();
}

// ---------------- the whole network, one persistent kernel -------------------
__global__ __launch_bounds__(TB, 4) void fused_gnn(
    const float* __restrict__ x,
    const int*   __restrict__ ei,
    const float* __restrict__ w_rel1, const float* __restrict__ b_rel1,
    const float* __restrict__ w_root1,
    const float* __restrict__ w_rel2, const float* __restrict__ b_rel2,
    const float* __restrict__ w_root2,
    float* __restrict__ out)
{
    __shared__ float s_w1[2][IN_CH * HID];
    __shared__ float s_b1[HID];
    __shared__ float s_w2[2][HID * NCLS];
    __shared__ float s_b2[NCLS];

    const unsigned nb  = gridDim.x;
    const int      T   = nb * TB;
    const int      tid = blockIdx.x * TB + threadIdx.x;
    const unsigned base = *(volatile unsigned*)&g_bar_base;

    for (int i = threadIdx.x; i < IN_CH * HID; i += TB) {
        s_w1[0][i] = w_rel1[i];
        s_w1[1][i] = w_root1[i];
    }
    for (int i = threadIdx.x; i < HID * NCLS; i += TB) {
        s_w2[0][i] = w_rel2[i];
        s_w2[1][i] = w_root2[i];
    }
    if (threadIdx.x < HID)  s_b1[threadIdx.x] = b_rel1[threadIdx.x];
    if (threadIdx.x < NCLS) s_b2[threadIdx.x] = b_rel2[threadIdx.x];
    if (tid == 0) {
        int all_zero = 1;                       // int64 => odd 32-bit words all 0
#pragma unroll
        for (int i = 0; i < 16; i++)
            if (ei[2 * i + 1] != 0) all_zero = 0;
        g_is64 = all_zero;
    }
    __syncthreads();

    // ---- Phase A: layer-1 projections (4 items / node) ----------------------
    for (int it = tid; it < N_NODES * 4; it += T) {
        int node = it >> 2;
        int sub  = it & 3;
        int mat  = sub >> 1;                    // 0: w_rel1 -> y1 ; 1: w_root1+b -> agg1
        int half = sub & 1;                     // output cols 8*half..8*half+7
        const float* w = s_w1[mat] + half * 8;

        float acc[8];
#pragma unroll
        for (int j = 0; j < 8; j++) acc[j] = mat ? s_b1[half * 8 + j] : 0.f;

        const float4* xr = reinterpret_cast<const float4*>(x + (size_t)node * IN_CH);
#pragma unroll
        for (int k4 = 0; k4 < IN_CH / 4; k4++) {
            float4 xv = __ldg(xr + k4);
            const float xs[4] = {xv.x, xv.y, xv.z, xv.w};
#pragma unroll
            for (int kk = 0; kk < 4; kk++) {
                float v = xs[kk];
                const float* wr = w + (k4 * 4 + kk) * HID;
#pragma unroll
                for (int j = 0; j < 8; j++) acc[j] = fmaf(v, wr[j], acc[j]);
            }
        }
        float* dstbuf = mat ? g_agg1 : g_y1;
        float4* op = reinterpret_cast<float4*>(dstbuf + (size_t)node * HID + half * 8);
        op[0] = make_float4(acc[0], acc[1], acc[2], acc[3]);
        op[1] = make_float4(acc[4], acc[5], acc[6], acc[7]);
    }
    gbar(1, base, nb);
    const int is64 = g_is64;

    // ---- Phase B: edge scatter, layer 1 (4-lane groups x 4 edges) -----------
    for (int it = tid; it < N_EDGES; it += T) {
        int q4 = (it & 3) * 4;
        int eb = (it >> 2) * 4;
        int4 sv = load_idx4(ei, is64, eb);
        int4 dv = load_idx4(ei, is64, N_EDGES + eb);
        int s0 = clampN(sv.x), s1 = clampN(sv.y), s2 = clampN(sv.z), s3 = clampN(sv.w);
        int d0 = clampN(dv.x), d1 = clampN(dv.y), d2 = clampN(dv.z), d3 = clampN(dv.w);
        float4 v0 = *reinterpret_cast<const float4*>(g_y1 + (size_t)s0 * HID + q4);
        float4 v1 = *reinterpret_cast<const float4*>(g_y1 + (size_t)s1 * HID + q4);
        float4 v2 = *reinterpret_cast<const float4*>(g_y1 + (size_t)s2 * HID + q4);
        float4 v3 = *reinterpret_cast<const float4*>(g_y1 + (size_t)s3 * HID + q4);
        red_add_v4(g_agg1 + (size_t)d0 * HID + q4, v0);
        red_add_v4(g_agg1 + (size_t)d1 * HID + q4, v1);
        red_add_v4(g_agg1 + (size_t)d2 * HID + q4, v2);
        red_add_v4(g_agg1 + (size_t)d3 * HID + q4, v3);
    }
    gbar(2, base, nb);

    // ---- Phase C: relu + layer-2 projections (2 items / node) ---------------
    for (int it = tid; it < N_NODES * 2; it += T) {
        int node = it >> 1;
        int mat  = it & 1;
        const float* w = s_w2[mat];

        float h[HID];
        const float4* a1p = reinterpret_cast<const float4*>(g_agg1 + (size_t)node * HID);
#pragma unroll
        for (int j = 0; j < HID / 4; j++) {
            float4 v = a1p[j];
            h[4*j]   = fmaxf(v.x, 0.f);
            h[4*j+1] = fmaxf(v.y, 0.f);
            h[4*j+2] = fmaxf(v.z, 0.f);
            h[4*j+3] = fmaxf(v.w, 0.f);
        }
        float acc[NCLS];
#pragma unroll
        for (int j = 0; j < NCLS; j++) acc[j] = mat ? s_b2[j] : 0.f;
#pragma unroll
        for (int k = 0; k < HID; k++) {
            float v = h[k];
#pragma unroll
            for (int j = 0; j < NCLS; j++) acc[j] = fmaf(v, w[k * NCLS + j], acc[j]);
        }
        float* dstbuf = mat ? g_agg2 : g_y2;
        float4* op = reinterpret_cast<float4*>(dstbuf + (size_t)node * L2S);
        op[0] = make_float4(acc[0], acc[1], acc[2], acc[3]);
        op[1] = make_float4(acc[4], acc[5], acc[6], acc[7]);
        op[2] = make_float4(acc[8], acc[9], 0.f, 0.f);
        op[3] = make_float4(0.f, 0.f, 0.f, 0.f);
    }
    gbar(3, base, nb);

    // ---- Phase D: edge scatter, layer 2 (64B zero-padded rows) --------------
    for (int it = tid; it < N_EDGES; it += T) {
        int q4 = (it & 3) * 4;
        int eb = (it >> 2) * 4;
        int4 sv = load_idx4(ei, is64, eb);
        int4 dv = load_idx4(ei, is64, N_EDGES + eb);
        int s0 = clampN(sv.x), s1 = clampN(sv.y), s2 = clampN(sv.z), s3 = clampN(sv.w);
        int d0 = clampN(dv.x), d1 = clampN(dv.y), d2 = clampN(dv.z), d3 = clampN(dv.w);
        float4 v0 = *reinterpret_cast<const float4*>(g_y2 + (size_t)s0 * L2S + q4);
        float4 v1 = *reinterpret_cast<const float4*>(g_y2 + (size_t)s1 * L2S + q4);
        float4 v2 = *reinterpret_cast<const float4*>(g_y2 + (size_t)s2 * L2S + q4);
        float4 v3 = *reinterpret_cast<const float4*>(g_y2 + (size_t)s3 * L2S + q4);
        red_add_v4(g_agg2 + (size_t)d0 * L2S + q4, v0);
        red_add_v4(g_agg2 + (size_t)d1 * L2S + q4, v1);
        red_add_v4(g_agg2 + (size_t)d2 * L2S + q4, v2);
        red_add_v4(g_agg2 + (size_t)d3 * L2S + q4, v3);
    }
    gbar(4, base, nb);

    // ---- Phase E: log_softmax ----------------------------------------------
    for (int node = tid; node < N_NODES; node += T) {
        const float* ap = g_agg2 + (size_t)node * L2S;
        float v[NCLS];
        float m = -3.4e38f;
#pragma unroll
        for (int j = 0; j < NCLS; j++) { v[j] = ap[j]; m = fmaxf(m, v[j]); }
        float s = 0.f;
#pragma unroll
        for (int j = 0; j < NCLS; j++) s += __expf(v[j] - m);
        float lse = __logf(s) + m;
        float* op = out + (size_t)node * NCLS;
#pragma unroll
        for (int j = 0; j < NCLS; j++) op[j] = v[j] - lse;
    }

    // Advance barrier base for the next replay. All blocks have passed gbar(4)
    // arrivals (cnt == base + 4*nb) before any block reaches here; spinners
    // only read g_bar_cnt, never g_bar_base, so this write races with nothing.
    if (tid == 0) {
        __threadfence();
        *(volatile unsigned*)&g_bar_base = base + 4u * nb;
    }
}

// ---------------- launch -----------------------------------------------------
extern "C" void kernel_launch(void* const* d_in, const int* in_sizes, int n_in,
                              void* d_out, int out_size) {
    const float* x       = (const float*)d_in[0];
    const int*   ei      = (const int*)d_in[1];   // dtype resolved by inline probe
    const float* w_rel1  = (const float*)d_in[2];
    const float* b_rel1  = (const float*)d_in[3];
    const float* w_root1 = (const float*)d_in[4];
    const float* w_rel2  = (const float*)d_in[5];
    const float* b_rel2  = (const float*)d_in[6];
    const float* w_root2 = (const float*)d_in[7];
    float* out = (float*)d_out;

    int dev = 0, sm = 0;
    cudaGetDevice(&dev);
    cudaDeviceGetAttribute(&sm, cudaDevAttrMultiProcessorCount, dev);
    if (sm <= 0) sm = 148;
    int nb = sm * 4;    // 4 blocks/SM guaranteed resident by __launch_bounds__(256,4)

    fused_gnn<<<nb, TB>>>(x, ei, w_rel1, b_rel1, w_root1,
                          w_rel2, b_rel2, w_root2, out);
}

// round 14
// speedup vs baseline: 1.1714x; 1.1714x over previous
#include <cuda_runtime.h>
#include <cuda_fp16.h>
#include <cstdint>

#define N_NODES  50000
#define N_EDGES  1600000
#define IN_CH    64
#define HID      16
#define NCLS     10
#define L2S      16   // fp32 accumulator row stride (64B)

// ---------------- scratch (device globals; no allocations allowed) ----------
__device__ __align__(16) __half g_y1h[N_NODES * 16];    // x @ w_rel1, fp16 (32B rows)
__device__ __align__(32) float  g_agg1[N_NODES * HID];  // x @ w_root1 + b (fp32 RMW target)
__device__ __align__(16) __half g_y2h[N_NODES * 16];    // h @ w_rel2, fp16, halves 10-15 = 0
__device__ __align__(32) float  g_agg2[N_NODES * L2S];  // h @ w_root2 + b, cols 10-15 = 0
__device__ int g_is64;                                  // edge_index dtype flag

// ---------------- vector reduction -------------------------------------------
__device__ __forceinline__ void red_add_v4(float* p, float4 v) {
    asm volatile("red.global.add.v4.f32 [%0], {%1,%2,%3,%4};"
                 :: "l"(p), "f"(v.x), "f"(v.y), "f"(v.z), "f"(v.w) : "memory");
}

__device__ __forceinline__ int clampN(int v) {
    return (int)min((unsigned)v, (unsigned)(N_NODES - 1));
}

// Pack 4 floats -> 4 halves (8B).
__device__ __forceinline__ uint2 pack_h4(float a, float b, float c, float d) {
    __half2 lo = __floats2half2_rn(a, b);
    __half2 hi = __floats2half2_rn(c, d);
    uint2 r;
    r.x = *reinterpret_cast<unsigned*>(&lo);
    r.y = *reinterpret_cast<unsigned*>(&hi);
    return r;
}

// ---------------- kernel 1: layer-1 projections (4 threads / node) ----------
// sub: mat = sub>>1 (0: w_rel1 -> y1h fp16 ; 1: w_root1 + b -> agg1 fp32 seed)
//      half = sub&1 (output cols 8*half..8*half+7)
// Block0/t0 probes the edge_index dtype (int64 high words all zero).
__global__ void layer1_node(const float* __restrict__ x,
                            const float* __restrict__ w_rel1,
                            const float* __restrict__ b_rel1,
                            const float* __restrict__ w_root1,
                            const int*   __restrict__ ei) {
    int gid = blockIdx.x * blockDim.x + threadIdx.x;
    if (gid == 0) {
        int all_zero = 1;
#pragma unroll
        for (int i = 0; i < 16; i++)
            if (ei[2 * i + 1] != 0) all_zero = 0;
        g_is64 = all_zero;
    }

    __shared__ float s_w[2][IN_CH * HID];
    __shared__ float s_b[HID];
    for (int i = threadIdx.x; i < IN_CH * HID; i += blockDim.x) {
        s_w[0][i] = w_rel1[i];
        s_w[1][i] = w_root1[i];
    }
    if (threadIdx.x < HID) s_b[threadIdx.x] = b_rel1[threadIdx.x];
    __syncthreads();

    int node = gid >> 2;
    if (node >= N_NODES) return;
    int sub  = gid & 3;
    int mat  = sub >> 1;
    int half = sub & 1;
    const float* w = s_w[mat] + half * 8;

    float acc[8];
#pragma unroll
    for (int j = 0; j < 8; j++) acc[j] = mat ? s_b[half * 8 + j] : 0.f;

    const float4* xr = reinterpret_cast<const float4*>(x + (size_t)node * IN_CH);
#pragma unroll
    for (int k4 = 0; k4 < IN_CH / 4; k4++) {
        float4 xv = __ldg(xr + k4);
        const float xs[4] = {xv.x, xv.y, xv.z, xv.w};
#pragma unroll
        for (int kk = 0; kk < 4; kk++) {
            float v = xs[kk];
            const float* wr = w + (k4 * 4 + kk) * HID;
#pragma unroll
            for (int j = 0; j < 8; j++) acc[j] = fmaf(v, wr[j], acc[j]);
        }
    }

    if (mat == 0) {
        // y1 fp16: 8 halves = 16B
        uint2* op = reinterpret_cast<uint2*>(g_y1h + (size_t)node * 16 + half * 8);
        op[0] = pack_h4(acc[0], acc[1], acc[2], acc[3]);
        op[1] = pack_h4(acc[4], acc[5], acc[6], acc[7]);
    } else {
        float4* op = reinterpret_cast<float4*>(g_agg1 + (size_t)node * HID + half * 8);
        op[0] = make_float4(acc[0], acc[1], acc[2], acc[3]);
        op[1] = make_float4(acc[4], acc[5], acc[6], acc[7]);
    }
}

// ---------------- kernel 2: edge scatter, layer 1 (4 threads / edge) ---------
// R3 shape: one 8B fp16 gather + one v4 fp32 red per thread, MLP_p1 ~ 1.
// Lane q handles halves q*4..q*4+3 of the 32B y1h row -> floats q*4.. of agg1.
__global__ void scatter1(const int* __restrict__ ei) {
    int idx = blockIdx.x * blockDim.x + threadIdx.x;
    int e = idx >> 2;
    if (e >= N_EDGES) return;
    int q = idx & 3;
    int off = g_is64 ? 2 : 1;                 // int64: read low words only
    int src = clampN(__ldg(ei + (size_t)e * off));
    int dst = clampN(__ldg(ei + ((size_t)N_EDGES + e) * off));
    uint2 raw = *reinterpret_cast<const uint2*>(g_y1h + (size_t)src * 16 + q * 4);
    __half2 h0 = *reinterpret_cast<__half2*>(&raw.x);
    __half2 h1 = *reinterpret_cast<__half2*>(&raw.y);
    float2 f0 = __half22float2(h0);
    float2 f1 = __half22float2(h1);
    red_add_v4(g_agg1 + (size_t)dst * HID + q * 4,
               make_float4(f0.x, f0.y, f1.x, f1.y));
}

// ---------------- kernel 3: relu + layer-2 projections (2 threads / node) ---
// mat = tid&1 : 0 -> y2h fp16 (halves 10-15 zero) ; 1 -> agg2 fp32 (cols 10-15 zero)
__global__ void layer2_node(const float* __restrict__ w_rel2,
                            const float* __restrict__ b_rel2,
                            const float* __restrict__ w_root2) {
    __shared__ float s_w[2][HID * NCLS];
    __shared__ float s_b[NCLS];
    for (int i = threadIdx.x; i < HID * NCLS; i += blockDim.x) {
        s_w[0][i] = w_rel2[i];
        s_w[1][i] = w_root2[i];
    }
    if (threadIdx.x < NCLS) s_b[threadIdx.x] = b_rel2[threadIdx.x];
    __syncthreads();

    int gid  = blockIdx.x * blockDim.x + threadIdx.x;
    int node = gid >> 1;
    if (node >= N_NODES) return;
    int mat  = gid & 1;
    const float* w = s_w[mat];

    float h[HID];
    const float4* a1p = reinterpret_cast<const float4*>(g_agg1 + (size_t)node * HID);
#pragma unroll
    for (int j = 0; j < HID / 4; j++) {
        float4 v = a1p[j];
        h[4*j]   = fmaxf(v.x, 0.f);
        h[4*j+1] = fmaxf(v.y, 0.f);
        h[4*j+2] = fmaxf(v.z, 0.f);
        h[4*j+3] = fmaxf(v.w, 0.f);
    }

    float acc[NCLS];
#pragma unroll
    for (int j = 0; j < NCLS; j++) acc[j] = mat ? s_b[j] : 0.f;
#pragma unroll
    for (int k = 0; k < HID; k++) {
        float v = h[k];
#pragma unroll
        for (int j = 0; j < NCLS; j++) acc[j] = fmaf(v, w[k * NCLS + j], acc[j]);
    }

    if (mat == 0) {
        uint2* op = reinterpret_cast<uint2*>(g_y2h + (size_t)node * 16);
        op[0] = pack_h4(acc[0], acc[1], acc[2], acc[3]);
        op[1] = pack_h4(acc[4], acc[5], acc[6], acc[7]);
        op[2] = pack_h4(acc[8], acc[9], 0.f, 0.f);
        op[3] = pack_h4(0.f, 0.f, 0.f, 0.f);
    } else {
        float4* op = reinterpret_cast<float4*>(g_agg2 + (size_t)node * L2S);
        op[0] = make_float4(acc[0], acc[1], acc[2], acc[3]);
        op[1] = make_float4(acc[4], acc[5], acc[6], acc[7]);
        op[2] = make_float4(acc[8], acc[9], 0.f, 0.f);
        op[3] = make_float4(0.f, 0.f, 0.f, 0.f);
    }
}

// ---------------- kernel 4: edge scatter, layer 2 (4 threads / edge) ---------
// Same shape as scatter1 on y2h/agg2 (zero-padded, fully uniform lanes).
__global__ void scatter2(const int* __restrict__ ei) {
    int idx = blockIdx.x * blockDim.x + threadIdx.x;
    int e = idx >> 2;
    if (e >= N_EDGES) return;
    int q = idx & 3;
    int off = g_is64 ? 2 : 1;
    int src = clampN(__ldg(ei + (size_t)e * off));
    int dst = clampN(__ldg(ei + ((size_t)N_EDGES + e) * off));
    uint2 raw = *reinterpret_cast<const uint2*>(g_y2h + (size_t)src * 16 + q * 4);
    __half2 h0 = *reinterpret_cast<__half2*>(&raw.x);
    __half2 h1 = *reinterpret_cast<__half2*>(&raw.y);
    float2 f0 = __half22float2(h0);
    float2 f1 = __half22float2(h1);
    red_add_v4(g_agg2 + (size_t)dst * L2S + q * 4,
               make_float4(f0.x, f0.y, f1.x, f1.y));
}

// ---------------- kernel 5: log_softmax ------------------------------------
__global__ void lsm_kernel(float* __restrict__ out) {
    int node = blockIdx.x * blockDim.x + threadIdx.x;
    if (node >= N_NODES) return;
    const float* ap = g_agg2 + (size_t)node * L2S;
    float v[NCLS];
    float m = -3.4e38f;
#pragma unroll
    for (int j = 0; j < NCLS; j++) { v[j] = ap[j]; m = fmaxf(m, v[j]); }
    float s = 0.f;
#pragma unroll
    for (int j = 0; j < NCLS; j++) s += __expf(v[j] - m);
    float lse = __logf(s) + m;
    float* op = out + (size_t)node * NCLS;
#pragma unroll
    for (int j = 0; j < NCLS; j++) op[j] = v[j] - lse;
}

// ---------------- launch -----------------------------------------------------
extern "C" void kernel_launch(void* const* d_in, const int* in_sizes, int n_in,
                              void* d_out, int out_size) {
    const float* x       = (const float*)d_in[0];
    const int*   ei      = (const int*)d_in[1];   // dtype resolved by inline probe
    const float* w_rel1  = (const float*)d_in[2];
    const float* b_rel1  = (const float*)d_in[3];
    const float* w_root1 = (const float*)d_in[4];
    const float* w_rel2  = (const float*)d_in[5];
    const float* b_rel2  = (const float*)d_in[6];
    const float* w_root2 = (const float*)d_in[7];
    float* out = (float*)d_out;

    const int TB = 256;

    int l1blocks = (N_NODES * 4 + TB - 1) / TB;        // 4 threads / node
    layer1_node<<<l1blocks, TB>>>(x, w_rel1, b_rel1, w_root1, ei);

    long long ethreads = (long long)N_EDGES * 4;       // 4 threads / edge (R3 shape)
    int eblocks = (int)((ethreads + TB - 1) / TB);
    scatter1<<<eblocks, TB>>>(ei);

    int l2blocks = (N_NODES * 2 + TB - 1) / TB;        // 2 threads / node
    layer2_node<<<l2blocks, TB>>>(w_rel2, b_rel2, w_root2);

    scatter2<<<eblocks, TB>>>(ei);

    int nodeBlocks = (N_NODES + TB - 1) / TB;
    lsm_kernel<<<nodeBlocks, TB>>>(out);
}

// round 15
// speedup vs baseline: 1.2184x; 1.0401x over previous
#include <cuda_runtime.h>
#include <cuda_fp16.h>
#include <cstdint>

#define N_NODES  50000
#define N_EDGES  1600000
#define IN_CH    64
#define HID      16
#define NCLS     10
#define L2S      12   // layer-2 fp32 accumulator stride: 48B rows, 16B aligned
#define Y2S      12   // layer-2 fp16 row stride: 24B rows (halves 10-11 zero)

// ---------------- scratch (device globals; no allocations allowed) ----------
__device__ __align__(16) __half g_y1h[N_NODES * 16];    // x @ w_rel1, fp16 (32B rows)
__device__ __align__(32) float  g_agg1[N_NODES * HID];  // x @ w_root1 + b (fp32 RMW target)
__device__ __align__(16) __half g_y2h[N_NODES * Y2S];   // h @ w_rel2, fp16 (24B rows)
__device__ __align__(16) float  g_agg2[N_NODES * L2S];  // h @ w_root2 + b (48B rows)
__device__ int g_is64;                                  // edge_index dtype flag

// ---------------- vector reduction -------------------------------------------
__device__ __forceinline__ void red_add_v4(float* p, float4 v) {
    asm volatile("red.global.add.v4.f32 [%0], {%1,%2,%3,%4};"
                 :: "l"(p), "f"(v.x), "f"(v.y), "f"(v.z), "f"(v.w) : "memory");
}

__device__ __forceinline__ int clampN(int v) {
    return (int)min((unsigned)v, (unsigned)(N_NODES - 1));
}

// Pack 4 floats -> 4 halves (8B).
__device__ __forceinline__ uint2 pack_h4(float a, float b, float c, float d) {
    __half2 lo = __floats2half2_rn(a, b);
    __half2 hi = __floats2half2_rn(c, d);
    uint2 r;
    r.x = *reinterpret_cast<unsigned*>(&lo);
    r.y = *reinterpret_cast<unsigned*>(&hi);
    return r;
}

// Unpack 8B (4 halves) -> float4.
__device__ __forceinline__ float4 unpack_h4(uint2 raw) {
    __half2 h0 = *reinterpret_cast<__half2*>(&raw.x);
    __half2 h1 = *reinterpret_cast<__half2*>(&raw.y);
    float2 f0 = __half22float2(h0);
    float2 f1 = __half22float2(h1);
    return make_float4(f0.x, f0.y, f1.x, f1.y);
}

// Fetch 4 consecutive edge srcs (or dsts) starting at elem index base (base%4==0).
__device__ __forceinline__ int4 load_idx4(const int* ei, int is64, int base) {
    if (!is64) {
        return __ldg(reinterpret_cast<const int4*>(ei + base));
    } else {
        const longlong2* p = reinterpret_cast<const longlong2*>(ei) + (base >> 1);
        longlong2 a = __ldg(p);
        longlong2 b = __ldg(p + 1);
        return make_int4((int)a.x, (int)a.y, (int)b.x, (int)b.y);
    }
}

// ---------------- kernel 1: layer-1 projections (4 threads / node) ----------
__global__ void layer1_node(const float* __restrict__ x,
                            const float* __restrict__ w_rel1,
                            const float* __restrict__ b_rel1,
                            const float* __restrict__ w_root1,
                            const int*   __restrict__ ei) {
    int gid = blockIdx.x * blockDim.x + threadIdx.x;
    if (gid == 0) {
        int all_zero = 1;                      // int64 => odd 32-bit words all 0
#pragma unroll
        for (int i = 0; i < 16; i++)
            if (ei[2 * i + 1] != 0) all_zero = 0;
        g_is64 = all_zero;
    }

    __shared__ float s_w[2][IN_CH * HID];
    __shared__ float s_b[HID];
    for (int i = threadIdx.x; i < IN_CH * HID; i += blockDim.x) {
        s_w[0][i] = w_rel1[i];
        s_w[1][i] = w_root1[i];
    }
    if (threadIdx.x < HID) s_b[threadIdx.x] = b_rel1[threadIdx.x];
    __syncthreads();

    int node = gid >> 2;
    if (node >= N_NODES) return;
    int sub  = gid & 3;
    int mat  = sub >> 1;                       // 0: w_rel1 -> y1h ; 1: w_root1+b -> agg1
    int half = sub & 1;                        // output cols 8*half..8*half+7
    const float* w = s_w[mat] + half * 8;

    float acc[8];
#pragma unroll
    for (int j = 0; j < 8; j++) acc[j] = mat ? s_b[half * 8 + j] : 0.f;

    const float4* xr = reinterpret_cast<const float4*>(x + (size_t)node * IN_CH);
#pragma unroll
    for (int k4 = 0; k4 < IN_CH / 4; k4++) {
        float4 xv = __ldg(xr + k4);
        const float xs[4] = {xv.x, xv.y, xv.z, xv.w};
#pragma unroll
        for (int kk = 0; kk < 4; kk++) {
            float v = xs[kk];
            const float* wr = w + (k4 * 4 + kk) * HID;
#pragma unroll
            for (int j = 0; j < 8; j++) acc[j] = fmaf(v, wr[j], acc[j]);
        }
    }

    if (mat == 0) {
        uint2* op = reinterpret_cast<uint2*>(g_y1h + (size_t)node * 16 + half * 8);
        op[0] = pack_h4(acc[0], acc[1], acc[2], acc[3]);
        op[1] = pack_h4(acc[4], acc[5], acc[6], acc[7]);
    } else {
        float4* op = reinterpret_cast<float4*>(g_agg1 + (size_t)node * HID + half * 8);
        op[0] = make_float4(acc[0], acc[1], acc[2], acc[3]);
        op[1] = make_float4(acc[4], acc[5], acc[6], acc[7]);
    }
}

// ---------------- kernel 2: edge scatter, layer 1 ----------------------------
// R10 shape: 4-lane groups x 4 edges, int4 index loads, branch-free clamp.
// Lane q: 8B fp16 gather (quarter q of the 32B y1h row) -> v4 fp32 red.
__global__ void scatter1(const int* __restrict__ ei) {
    int gid  = blockIdx.x * blockDim.x + threadIdx.x;
    int q4   = (gid & 3) * 4;                 // float offset within agg1 row
    int qh   = (gid & 3) * 4;                 // half offset within y1h row
    int base = (gid >> 2) * 4;
    if (base >= N_EDGES) return;              // N_EDGES % 4 == 0, no tail
    int is64 = g_is64;
    int4 sv = load_idx4(ei, is64, base);
    int4 dv = load_idx4(ei, is64, N_EDGES + base);
    int s0 = clampN(sv.x), s1 = clampN(sv.y), s2 = clampN(sv.z), s3 = clampN(sv.w);
    int d0 = clampN(dv.x), d1 = clampN(dv.y), d2 = clampN(dv.z), d3 = clampN(dv.w);
    float4 v0 = unpack_h4(*reinterpret_cast<const uint2*>(g_y1h + (size_t)s0 * 16 + qh));
    float4 v1 = unpack_h4(*reinterpret_cast<const uint2*>(g_y1h + (size_t)s1 * 16 + qh));
    float4 v2 = unpack_h4(*reinterpret_cast<const uint2*>(g_y1h + (size_t)s2 * 16 + qh));
    float4 v3 = unpack_h4(*reinterpret_cast<const uint2*>(g_y1h + (size_t)s3 * 16 + qh));
    red_add_v4(g_agg1 + (size_t)d0 * HID + q4, v0);
    red_add_v4(g_agg1 + (size_t)d1 * HID + q4, v1);
    red_add_v4(g_agg1 + (size_t)d2 * HID + q4, v2);
    red_add_v4(g_agg1 + (size_t)d3 * HID + q4, v3);
}

// ---------------- kernel 3: relu + layer-2 projections (2 threads / node) ---
// mat = tid&1 : 0 -> y2h fp16 (24B rows, halves 10-11 zero)
//               1 -> agg2 fp32 (48B rows, cols 10-11 zero)
__global__ void layer2_node(const float* __restrict__ w_rel2,
                            const float* __restrict__ b_rel2,
                            const float* __restrict__ w_root2) {
    __shared__ float s_w[2][HID * NCLS];
    __shared__ float s_b[NCLS];
    for (int i = threadIdx.x; i < HID * NCLS; i += blockDim.x) {
        s_w[0][i] = w_rel2[i];
        s_w[1][i] = w_root2[i];
    }
    if (threadIdx.x < NCLS) s_b[threadIdx.x] = b_rel2[threadIdx.x];
    __syncthreads();

    int gid  = blockIdx.x * blockDim.x + threadIdx.x;
    int node = gid >> 1;
    if (node >= N_NODES) return;
    int mat  = gid & 1;
    const float* w = s_w[mat];

    float h[HID];
    const float4* a1p = reinterpret_cast<const float4*>(g_agg1 + (size_t)node * HID);
#pragma unroll
    for (int j = 0; j < HID / 4; j++) {
        float4 v = a1p[j];
        h[4*j]   = fmaxf(v.x, 0.f);
        h[4*j+1] = fmaxf(v.y, 0.f);
        h[4*j+2] = fmaxf(v.z, 0.f);
        h[4*j+3] = fmaxf(v.w, 0.f);
    }

    float acc[NCLS];
#pragma unroll
    for (int j = 0; j < NCLS; j++) acc[j] = mat ? s_b[j] : 0.f;
#pragma unroll
    for (int k = 0; k < HID; k++) {
        float v = h[k];
#pragma unroll
        for (int j = 0; j < NCLS; j++) acc[j] = fmaf(v, w[k * NCLS + j], acc[j]);
    }

    if (mat == 0) {
        uint2* op = reinterpret_cast<uint2*>(g_y2h + (size_t)node * Y2S);
        op[0] = pack_h4(acc[0], acc[1], acc[2], acc[3]);
        op[1] = pack_h4(acc[4], acc[5], acc[6], acc[7]);
        op[2] = pack_h4(acc[8], acc[9], 0.f, 0.f);
    } else {
        float4* op = reinterpret_cast<float4*>(g_agg2 + (size_t)node * L2S);
        op[0] = make_float4(acc[0], acc[1], acc[2], acc[3]);
        op[1] = make_float4(acc[4], acc[5], acc[6], acc[7]);
        op[2] = make_float4(acc[8], acc[9], 0.f, 0.f);
    }
}

// ---------------- kernel 4: edge scatter, layer 2 ----------------------------
// Uniform 3 lanes / edge on 48B rows: every lane does one 8B fp16 gather and
// one v4 fp32 red (cols 10-11 are zero padding). No divergence, no idle lanes.
__global__ void scatter2(const int* __restrict__ ei) {
    int idx = blockIdx.x * blockDim.x + threadIdx.x;
    int e = idx / 3;
    if (e >= N_EDGES) return;
    int q = idx - e * 3;                      // 0,1,2
    int off = g_is64 ? 2 : 1;
    int src = clampN(__ldg(ei + (size_t)e * off));
    int dst = clampN(__ldg(ei + ((size_t)N_EDGES + e) * off));
    float4 v = unpack_h4(*reinterpret_cast<const uint2*>(g_y2h + (size_t)src * Y2S + q * 4));
    red_add_v4(g_agg2 + (size_t)dst * L2S + q * 4, v);
}

// ---------------- kernel 5: log_softmax ------------------------------------
__global__ void lsm_kernel(float* __restrict__ out) {
    int node = blockIdx.x * blockDim.x + threadIdx.x;
    if (node >= N_NODES) return;
    const float* ap = g_agg2 + (size_t)node * L2S;
    float v[NCLS];
    float m = -3.4e38f;
#pragma unroll
    for (int j = 0; j < NCLS; j++) { v[j] = ap[j]; m = fmaxf(m, v[j]); }
    float s = 0.f;
#pragma unroll
    for (int j = 0; j < NCLS; j++) s += __expf(v[j] - m);
    float lse = __logf(s) + m;
    float* op = out + (size_t)node * NCLS;
#pragma unroll
    for (int j = 0; j < NCLS; j++) op[j] = v[j] - lse;
}

// ---------------- launch -----------------------------------------------------
extern "C" void kernel_launch(void* const* d_in, const int* in_sizes, int n_in,
                              void* d_out, int out_size) {
    const float* x       = (const float*)d_in[0];
    const int*   ei      = (const int*)d_in[1];   // dtype resolved by inline probe
    const float* w_rel1  = (const float*)d_in[2];
    const float* b_rel1  = (const float*)d_in[3];
    const float* w_root1 = (const float*)d_in[4];
    const float* w_rel2  = (const float*)d_in[5];
    const float* b_rel2  = (const float*)d_in[6];
    const float* w_root2 = (const float*)d_in[7];
    float* out = (float*)d_out;

    const int TB = 256;

    int l1blocks = (N_NODES * 4 + TB - 1) / TB;        // 4 threads / node
    layer1_node<<<l1blocks, TB>>>(x, w_rel1, b_rel1, w_root1, ei);

    long long s1threads = (long long)(N_EDGES / 4) * 4; // 4 lanes x (E/4) groups
    int s1blocks = (int)((s1threads + TB - 1) / TB);
    scatter1<<<s1blocks, TB>>>(ei);

    int l2blocks = (N_NODES * 2 + TB - 1) / TB;        // 2 threads / node
    layer2_node<<<l2blocks, TB>>>(w_rel2, b_rel2, w_root2);

    long long s2threads = (long long)N_EDGES * 3;      // 3 lanes / edge
    int s2blocks = (int)((s2threads + TB - 1) / TB);
    scatter2<<<s2blocks, TB>>>(ei);

    int nodeBlocks = (N_NODES + TB - 1) / TB;
    lsm_kernel<<<nodeBlocks, TB>>>(out);
}